// round 3
// baseline (speedup 1.0000x reference)
#include <cuda_runtime.h>
#include <cstdint>

#define ENT_GRID 16
#define ENT_DIM  64
#define EMB_DIM  1024
#define LN_EPS   1e-5f
#define MAX_B    8192
#define MAX_R    5120     // padded; scan supports up to 5120

// ---------------- device scratch (no allocation allowed) ----------------
__device__ int g_ids_is64;
__device__ int g_hist[MAX_R];
__device__ int g_cursor[MAX_R];
__device__ int g_rows[MAX_B];     // batch indices sorted by relation id

__device__ __forceinline__ int get_id(const void* ids, int b) {
    if (g_ids_is64) return (int)reinterpret_cast<const long long*>(ids)[b];
    return reinterpret_cast<const int*>(ids)[b];
}

// ---------------- prepass 1: detect id dtype + zero histogram ----------------
// block 0: dtype sniff (odd 32-bit words all zero <=> int64, values < 5000).
// other blocks: zero g_hist.
__global__ void detect_and_zero_kernel(const int* __restrict__ w, int n_words, int R) {
    if (blockIdx.x == 0) {
        __shared__ int any_nonzero;
        if (threadIdx.x == 0) any_nonzero = 0;
        __syncthreads();
        for (int i = 1 + 2 * threadIdx.x; i < n_words; i += 2 * blockDim.x)
            if (w[i] != 0) any_nonzero = 1;
        __syncthreads();
        if (threadIdx.x == 0) g_ids_is64 = (any_nonzero == 0) ? 1 : 0;
    } else {
        int i = (blockIdx.x - 1) * blockDim.x + threadIdx.x;
        if (i < R) g_hist[i] = 0;
    }
}

// ---------------- prepass 2: histogram ----------------
__global__ void hist_kernel(const void* __restrict__ ids, int batch) {
    int b = blockIdx.x * blockDim.x + threadIdx.x;
    if (b < batch) atomicAdd(&g_hist[get_id(ids, b)], 1);
}

// ---------------- prepass 3: exclusive scan (single block) ----------------
// Writes exclusive prefix into g_cursor. Supports R <= 5120.
__global__ void scan_kernel(int R) {
    __shared__ int sh[1024];
    const int t = threadIdx.x;
    const int base = t * 5;
    int loc[5];
    int s = 0;
#pragma unroll
    for (int i = 0; i < 5; ++i) {
        int v = (base + i < R) ? g_hist[base + i] : 0;
        loc[i] = v; s += v;
    }
    sh[t] = s;
    __syncthreads();
    for (int o = 1; o < 1024; o <<= 1) {
        int v = (t >= o) ? sh[t - o] : 0;
        __syncthreads();
        sh[t] += v;
        __syncthreads();
    }
    int run = sh[t] - s;   // exclusive prefix of this thread's chunk
#pragma unroll
    for (int i = 0; i < 5; ++i) {
        if (base + i < R) {
            g_cursor[base + i] = run;
            run += loc[i];
        }
    }
}

// ---------------- prepass 4: scatter batch indices (counting sort) ----------------
__global__ void scatter_kernel(const void* __restrict__ ids, int batch) {
    int b = blockIdx.x * blockDim.x + threadIdx.x;
    if (b < batch) {
        int rel = get_id(ids, b);
        int pos = atomicAdd(&g_cursor[rel], 1);
        g_rows[pos] = b;
    }
}

// ---------------- main: one CTA per batch row, rows ordered by relation ----------------
// Identical compute structure to the proven R1 kernel; only the b mapping changed.
__global__ __launch_bounds__(256, 8)
void wproj_ln_kernel(
    const float* __restrict__ ent_emb,   // [B, 1024]
    const void*  __restrict__ proj_ids,  // [B]
    const float* __restrict__ tran,      // [R, 1024, 16]
    const float* __restrict__ bias,      // [R, 1024]
    const float* __restrict__ ln_w,
    const float* __restrict__ ln_b,
    float*       __restrict__ out)       // [B, 1024]
{
    const int b = g_rows[blockIdx.x];
    const int t = threadIdx.x;

    __shared__ float4 e4[EMB_DIM / 4];
    __shared__ float  red_s[8], red_s2[8];

    const float4* erow = reinterpret_cast<const float4*>(ent_emb + (size_t)b * EMB_DIM);
    e4[t] = erow[t];
    __syncthreads();

    const long long rel = (long long)get_id(proj_ids, b);
    const float* T  = tran + (size_t)rel * (EMB_DIM * ENT_GRID);
    const float* Bb = bias + (size_t)rel * EMB_DIM;

    float x[4];
    float s = 0.f, s2 = 0.f;

#pragma unroll
    for (int j = 0; j < 4; ++j) {
        const int r = t + j * 256;
        const int d = r >> 4;
        const float4* Trow = reinterpret_cast<const float4*>(T + (size_t)r * ENT_GRID);
        float acc = __ldg(Bb + r);
#pragma unroll
        for (int k = 0; k < 4; ++k) {
            const float4 tv = __ldg(Trow + k);
            const float4 ev = e4[d * 4 + k];
            acc += tv.x * ev.x + tv.y * ev.y + tv.z * ev.z + tv.w * ev.w;
        }
        x[j] = acc;
        s  += acc;
        s2 += acc * acc;
    }

#pragma unroll
    for (int o = 16; o > 0; o >>= 1) {
        s  += __shfl_xor_sync(0xffffffffu, s,  o);
        s2 += __shfl_xor_sync(0xffffffffu, s2, o);
    }
    const int wid = t >> 5, lid = t & 31;
    if (lid == 0) { red_s[wid] = s; red_s2[wid] = s2; }
    __syncthreads();
    if (wid == 0) {
        s  = (lid < 8) ? red_s[lid]  : 0.f;
        s2 = (lid < 8) ? red_s2[lid] : 0.f;
#pragma unroll
        for (int o = 4; o > 0; o >>= 1) {
            s  += __shfl_xor_sync(0xffffffffu, s,  o);
            s2 += __shfl_xor_sync(0xffffffffu, s2, o);
        }
        if (lid == 0) { red_s[0] = s; red_s2[0] = s2; }
    }
    __syncthreads();

    const float inv_n = 1.0f / (float)EMB_DIM;
    const float mean  = red_s[0] * inv_n;
    const float var   = red_s2[0] * inv_n - mean * mean;
    const float rstd  = rsqrtf(var + LN_EPS);

    float* ob = out + (size_t)b * EMB_DIM;
#pragma unroll
    for (int j = 0; j < 4; ++j) {
        const int r = t + j * 256;
        ob[r] = (x[j] - mean) * rstd * __ldg(ln_w + r) + __ldg(ln_b + r);
    }
}

// ---------------- launch ----------------
extern "C" void kernel_launch(void* const* d_in, const int* in_sizes, int n_in,
                              void* d_out, int out_size) {
    const float* ent_emb = (const float*)d_in[0];
    const void*  ids     = d_in[1];
    const float* tran    = (const float*)d_in[2];
    const float* bias    = (const float*)d_in[3];
    const float* ln_w    = (const float*)d_in[4];
    const float* ln_b    = (const float*)d_in[5];
    float*       out     = (float*)d_out;

    const int batch = in_sizes[0] / EMB_DIM;                 // 8192
    const int R     = in_sizes[2] / (EMB_DIM * ENT_GRID);    // 5000
    const int n_idw = in_sizes[1];                           // id element count

    // prepass: counting sort of batch rows by relation id
    detect_and_zero_kernel<<<(R + 255) / 256 + 1, 256>>>((const int*)ids, n_idw, R);
    hist_kernel<<<(batch + 255) / 256, 256>>>(ids, batch);
    scan_kernel<<<1, 1024>>>(R);
    scatter_kernel<<<(batch + 255) / 256, 256>>>(ids, batch);

    // main
    wproj_ln_kernel<<<batch, 256>>>(ent_emb, ids, tran, bias, ln_w, ln_b, out);
}